// round 1
// baseline (speedup 1.0000x reference)
#include <cuda_runtime.h>
#include <math.h>

// ---------------- problem constants ----------------
#define TSZ    480000
#define BATCH  8
#define CHUNK  4096
#define STRIDE 3072
#define NCH    157          // ceil(T/STRIDE)
#define NF     13           // frames per chunk
#define NFFT   1024
#define HOP    256
#define FBINS  513
#define HDIM   256
#define EDIM   128
#define N3H    768          // 3*H
#define SEQ    (BATCH*NCH)  // 1256 GRU sequences
#define ROWS   (SEQ*NF)     // 16328 frames total
#define PI_F   3.14159265358979323846f

// ---------------- scratch (device globals: allowed) ----------------
__device__ float g_mag [ROWS*FBINS];
__device__ float g_cosp[ROWS*FBINS];
__device__ float g_sinp[ROWS*FBINS];
__device__ float g_xg  [ROWS*N3H];
__device__ float g_hs  [ROWS*HDIM];
__device__ float g_gb  [ROWS*2*FBINS];
__device__ float g_y   [ROWS*NFFT];
__device__ float g_embrow[BATCH*N3H];
__device__ float g_wsum[CHUNK];

__device__ __forceinline__ float sigf(float x) { return 1.f/(1.f + expf(-x)); }

// ---------------- wsum precompute ----------------
__global__ void k_wsum() {
    int n = blockIdx.x*blockDim.x + threadIdx.x;
    if (n >= CHUNK) return;
    float ws = 0.f;
    for (int fi = 0; fi < NF; fi++) {
        int d = n - fi*HOP;
        if (d >= 0 && d < NFFT) {
            float w = 0.5f - 0.5f*cosf((2.f*PI_F/NFFT)*d);
            ws += w*w;
        }
    }
    g_wsum[n] = ws;
}

// ---------------- per-batch embedding contribution to xg ----------------
__global__ void k_embrow(const float* __restrict__ emb_table,
                         const float* __restrict__ wx,
                         const int*   __restrict__ effect_id) {
    __shared__ float se[EDIM];
    int b = blockIdx.x;
    int j = threadIdx.x;           // 0..767
    if (j < EDIM) se[j] = emb_table[effect_id[b]*EDIM + j];
    __syncthreads();
    float acc = 0.f;
    #pragma unroll 8
    for (int k = 0; k < EDIM; k++)
        acc += se[k] * wx[(FBINS + k)*N3H + j];
    g_embrow[b*N3H + j] = acc;
}

// ---------------- forward STFT: frame -> mag, cos, sin ----------------
__global__ void k_fwdfft(const float* __restrict__ audio) {
    __shared__ float sr[NFFT], si[NFFT];
    __shared__ float twr[512], twis[512];
    const int fr  = blockIdx.x;
    const int tid = threadIdx.x;
    const int b   = fr / (NCH*NF);
    const int rem = fr % (NCH*NF);
    const int ci  = rem / NF;
    const int fi  = rem % NF;
    const int base = ci*STRIDE + fi*HOP;

    for (int k = tid; k < 512; k += 256) {
        float s, c; sincosf(-(2.f*PI_F/NFFT)*k, &s, &c);
        twr[k] = c; twis[k] = s;
    }
    for (int n = tid; n < NFFT; n += 256) {
        int s = base + n;
        float v = (s < TSZ) ? audio[b*TSZ + s] : 0.f;
        float w = 0.5f - 0.5f*cosf((2.f*PI_F/NFFT)*n);
        int j = __brev((unsigned)n) >> 22;
        sr[j] = v*w; si[j] = 0.f;
    }
    __syncthreads();
    for (int s = 1; s <= 10; s++) {
        int half = 1 << (s-1);
        for (int t = tid; t < 512; t += 256) {
            int pos = t & (half-1);
            int grp = t >> (s-1);
            int i1 = (grp << s) + pos;
            int i2 = i1 + half;
            int ti_ = pos << (10 - s);
            float wr = twr[ti_], wi = twis[ti_];
            float xr = sr[i2], xi = si[i2];
            float tr = wr*xr - wi*xi;
            float tq = wr*xi + wi*xr;
            sr[i2] = sr[i1] - tr; si[i2] = si[i1] - tq;
            sr[i1] += tr;         si[i1] += tq;
        }
        __syncthreads();
    }
    for (int k = tid; k < FBINS; k += 256) {
        float re = sr[k], im = si[k];
        float mag = sqrtf(re*re + im*im);
        float c, s2;
        if (mag > 1e-30f) { float inv = 1.f/mag; c = re*inv; s2 = im*inv; }
        else              { c = 1.f; s2 = 0.f; }
        g_mag [fr*FBINS + k] = mag;
        g_cosp[fr*FBINS + k] = c;
        g_sinp[fr*FBINS + k] = s2;
    }
}

// ---------------- xg = mag @ Wx[:F] + embrow(b)  (M=ROWS, N=768, K=513) ----------------
__global__ void k_xg(const float* __restrict__ wx) {
    __shared__ float As[16][65];
    __shared__ float Bs[16][65];
    const int m0 = blockIdx.y * 64;
    const int n0 = blockIdx.x * 64;
    const int tid = threadIdx.x;
    const int ty = tid >> 4, tx = tid & 15;
    float acc[4][4] = {};
    for (int k0 = 0; k0 < FBINS; k0 += 16) {
        #pragma unroll
        for (int i = 0; i < 4; i++) {
            int lin = tid + i*256;
            int mm = lin >> 4, kk = lin & 15;
            int row = m0 + mm, k = k0 + kk;
            As[kk][mm] = (row < ROWS && k < FBINS) ? g_mag[row*FBINS + k] : 0.f;
        }
        #pragma unroll
        for (int i = 0; i < 4; i++) {
            int lin = tid + i*256;
            int kk = lin >> 6, nn = lin & 63;
            int k = k0 + kk;
            Bs[kk][nn] = (k < FBINS) ? wx[k*N3H + n0 + nn] : 0.f;
        }
        __syncthreads();
        #pragma unroll
        for (int kk = 0; kk < 16; kk++) {
            float a[4], bb[4];
            #pragma unroll
            for (int i = 0; i < 4; i++) a[i]  = As[kk][ty*4 + i];
            #pragma unroll
            for (int j = 0; j < 4; j++) bb[j] = Bs[kk][tx*4 + j];
            #pragma unroll
            for (int i = 0; i < 4; i++)
                #pragma unroll
                for (int j = 0; j < 4; j++)
                    acc[i][j] += a[i]*bb[j];
        }
        __syncthreads();
    }
    #pragma unroll
    for (int i = 0; i < 4; i++) {
        int row = m0 + ty*4 + i;
        if (row >= ROWS) continue;
        int b = row / (NCH*NF);
        #pragma unroll
        for (int j = 0; j < 4; j++) {
            int col = n0 + tx*4 + j;
            g_xg[row*N3H + col] = acc[i][j] + g_embrow[b*N3H + col];
        }
    }
}

// ---------------- one GRU step: hg = h@Wh + b, gates, write hs[t] ----------------
// block: 32 rows x 64 cols (same 64-col slice of all three gates)
__global__ void k_gru(const float* __restrict__ wh,
                      const float* __restrict__ gbias, int t) {
    __shared__ float As[16][33];
    __shared__ float Bs[3][16][65];
    const int sq0 = blockIdx.y * 32;
    const int c0  = blockIdx.x * 64;
    const int tid = threadIdx.x;
    const int ty = tid >> 4, tx = tid & 15;
    float acc[3][2][4] = {};
    if (t > 0) {
        for (int k0 = 0; k0 < HDIM; k0 += 16) {
            #pragma unroll
            for (int i = 0; i < 2; i++) {
                int lin = tid + i*256;
                int mm = lin >> 4, kk = lin & 15;
                int sq = sq0 + mm;
                As[kk][mm] = (sq < SEQ) ? g_hs[(sq*NF + t - 1)*HDIM + k0 + kk] : 0.f;
            }
            #pragma unroll
            for (int i = 0; i < 12; i++) {
                int lin = tid + i*256;
                int gg = lin >> 10;
                int r2 = lin & 1023;
                int kk = r2 >> 6, nn = r2 & 63;
                Bs[gg][kk][nn] = wh[(k0+kk)*N3H + gg*HDIM + c0 + nn];
            }
            __syncthreads();
            #pragma unroll
            for (int kk = 0; kk < 16; kk++) {
                float a0 = As[kk][ty*2], a1 = As[kk][ty*2 + 1];
                #pragma unroll
                for (int gg = 0; gg < 3; gg++) {
                    #pragma unroll
                    for (int j = 0; j < 4; j++) {
                        float bv = Bs[gg][kk][tx*4 + j];
                        acc[gg][0][j] += a0*bv;
                        acc[gg][1][j] += a1*bv;
                    }
                }
            }
            __syncthreads();
        }
    }
    #pragma unroll
    for (int i = 0; i < 2; i++) {
        int sq = sq0 + ty*2 + i;
        if (sq >= SEQ) continue;
        const float* xg = &g_xg[(sq*NF + t)*N3H];
        int hbase = (sq*NF + t)*HDIM;
        int pbase = (sq*NF + t - 1)*HDIM;
        #pragma unroll
        for (int j = 0; j < 4; j++) {
            int c = c0 + tx*4 + j;
            float z = sigf(xg[c]          + acc[0][i][j] + gbias[c]);
            float r = sigf(xg[HDIM + c]   + acc[1][i][j] + gbias[HDIM + c]);
            float n = tanhf(xg[2*HDIM + c] + r*(acc[2][i][j] + gbias[2*HDIM + c]));
            float hp = (t > 0) ? g_hs[pbase + c] : 0.f;
            g_hs[hbase + c] = (1.f - z)*n + z*hp;
        }
    }
}

// ---------------- proj: gb = hs @ proj_w + proj_b (M=ROWS, N=1026, K=256) ----------------
__global__ void k_proj(const float* __restrict__ pw,
                       const float* __restrict__ pb) {
    __shared__ float As[16][65];
    __shared__ float Bs[16][65];
    const int m0 = blockIdx.y * 64;
    const int n0 = blockIdx.x * 64;
    const int tid = threadIdx.x;
    const int ty = tid >> 4, tx = tid & 15;
    const int NN = 2*FBINS;  // 1026
    float acc[4][4] = {};
    for (int k0 = 0; k0 < HDIM; k0 += 16) {
        #pragma unroll
        for (int i = 0; i < 4; i++) {
            int lin = tid + i*256;
            int mm = lin >> 4, kk = lin & 15;
            int row = m0 + mm;
            As[kk][mm] = (row < ROWS) ? g_hs[row*HDIM + k0 + kk] : 0.f;
        }
        #pragma unroll
        for (int i = 0; i < 4; i++) {
            int lin = tid + i*256;
            int kk = lin >> 6, nn = lin & 63;
            int col = n0 + nn;
            Bs[kk][nn] = (col < NN) ? pw[(k0+kk)*NN + col] : 0.f;
        }
        __syncthreads();
        #pragma unroll
        for (int kk = 0; kk < 16; kk++) {
            float a[4], bb[4];
            #pragma unroll
            for (int i = 0; i < 4; i++) a[i]  = As[kk][ty*4 + i];
            #pragma unroll
            for (int j = 0; j < 4; j++) bb[j] = Bs[kk][tx*4 + j];
            #pragma unroll
            for (int i = 0; i < 4; i++)
                #pragma unroll
                for (int j = 0; j < 4; j++)
                    acc[i][j] += a[i]*bb[j];
        }
        __syncthreads();
    }
    #pragma unroll
    for (int i = 0; i < 4; i++) {
        int row = m0 + ty*4 + i;
        if (row >= ROWS) continue;
        #pragma unroll
        for (int j = 0; j < 4; j++) {
            int col = n0 + tx*4 + j;
            if (col < NN)
                g_gb[row*NN + col] = acc[i][j] + pb[col];
        }
    }
}

// ---------------- modulate + inverse FFT + window ----------------
__global__ void k_modinv() {
    __shared__ float sre[FBINS], sim[FBINS];
    __shared__ float sr[NFFT], si[NFFT];
    __shared__ float twr[512], twis[512];
    const int fr  = blockIdx.x;
    const int tid = threadIdx.x;

    for (int k = tid; k < 512; k += 256) {
        float s, c; sincosf(-(2.f*PI_F/NFFT)*k, &s, &c);
        twr[k] = c; twis[k] = s;
    }
    for (int k = tid; k < FBINS; k += 256) {
        float mag   = g_mag[fr*FBINS + k];
        float gamma = g_gb[fr*2*FBINS + k];
        float beta  = g_gb[fr*2*FBINS + FBINS + k];
        float mm = gamma*mag + beta;
        sre[k] = mm * g_cosp[fr*FBINS + k];
        sim[k] = mm * g_sinp[fr*FBINS + k];
    }
    __syncthreads();
    for (int n = tid; n < NFFT; n += 256) {
        float re, im;
        if (n <= 512) { re = sre[n];        im =  sim[n]; }
        else          { re = sre[NFFT - n]; im = -sim[NFFT - n]; }
        int j = __brev((unsigned)n) >> 22;
        sr[j] = re; si[j] = im;
    }
    __syncthreads();
    for (int s = 1; s <= 10; s++) {
        int half = 1 << (s-1);
        for (int t = tid; t < 512; t += 256) {
            int pos = t & (half-1);
            int grp = t >> (s-1);
            int i1 = (grp << s) + pos;
            int i2 = i1 + half;
            int ti_ = pos << (10 - s);
            float wr = twr[ti_], wi = -twis[ti_];   // conj: inverse transform
            float xr = sr[i2], xi = si[i2];
            float tr = wr*xr - wi*xi;
            float tq = wr*xi + wi*xr;
            sr[i2] = sr[i1] - tr; si[i2] = si[i1] - tq;
            sr[i1] += tr;         si[i1] += tq;
        }
        __syncthreads();
    }
    const float invn = 1.f/(float)NFFT;
    for (int n = tid; n < NFFT; n += 256) {
        float w = 0.5f - 0.5f*cosf((2.f*PI_F/NFFT)*n);
        g_y[fr*NFFT + n] = sr[n]*invn*w;
    }
}

// ---------------- overlap-add (frames within chunk, chunks within signal) ----------------
__global__ void k_overlap(float* __restrict__ out) {
    const int t = blockIdx.x*blockDim.x + threadIdx.x;
    const int b = blockIdx.y;
    if (t >= TSZ) return;
    int ci_hi = t / STRIDE; if (ci_hi > NCH-1) ci_hi = NCH-1;
    int v = t - (CHUNK - 1);
    int ci_lo = (v <= 0) ? 0 : (v + STRIDE - 1)/STRIDE;
    float acc = 0.f;
    for (int ci = ci_lo; ci <= ci_hi; ci++) {
        int n = t - ci*STRIDE;      // 0..CHUNK-1
        int fi_hi = n >> 8; if (fi_hi > NF-1) fi_hi = NF-1;
        int w = n - (NFFT - 1);
        int fi_lo = (w <= 0) ? 0 : (w + HOP - 1) >> 8;
        float s = 0.f;
        for (int fi = fi_lo; fi <= fi_hi; fi++)
            s += g_y[(((b*NCH + ci)*NF) + fi)*NFFT + n - fi*HOP];
        acc += s / fmaxf(g_wsum[n], 1e-8f);
    }
    out[b*TSZ + t] = acc;
}

// ---------------- launch ----------------
extern "C" void kernel_launch(void* const* d_in, const int* in_sizes, int n_in,
                              void* d_out, int out_size) {
    const float* audio     = (const float*)d_in[0];
    const float* emb_table = (const float*)d_in[1];
    const float* gru_wx    = (const float*)d_in[2];
    const float* gru_wh    = (const float*)d_in[3];
    const float* gru_b     = (const float*)d_in[4];
    const float* proj_w    = (const float*)d_in[5];
    const float* proj_b    = (const float*)d_in[6];
    const int*   effect_id = (const int*)  d_in[7];
    float* out = (float*)d_out;

    k_wsum<<<(CHUNK + 255)/256, 256>>>();
    k_embrow<<<BATCH, N3H>>>(emb_table, gru_wx, effect_id);
    k_fwdfft<<<ROWS, 256>>>(audio);
    k_xg<<<dim3(N3H/64, (ROWS + 63)/64), 256>>>(gru_wx);
    for (int t = 0; t < NF; t++)
        k_gru<<<dim3(HDIM/64, (SEQ + 31)/32), 256>>>(gru_wh, gru_b, t);
    k_proj<<<dim3((2*FBINS + 63)/64, (ROWS + 63)/64), 256>>>(proj_w, proj_b);
    k_modinv<<<ROWS, 256>>>();
    k_overlap<<<dim3((TSZ + 255)/256, BATCH), 256>>>(out);
}

// round 3
// speedup vs baseline: 1.1500x; 1.1500x over previous
#include <cuda_runtime.h>
#include <math.h>

// ---------------- problem constants ----------------
#define TSZ    480000
#define BATCH  8
#define CHUNK  4096
#define STRIDE 3072
#define NCH    157
#define NF     13
#define NFFT   1024
#define HOP    256
#define FBINS  513
#define HDIM   256
#define EDIM   128
#define N3H    768
#define SEQ    (BATCH*NCH)   // 1256
#define ROWS   (SEQ*NF)      // 16328
#define CPB    (NCH*NF)      // 2041 frames per batch
#define KPAD   528           // FBINS padded to mult of 16 (and float4)
#define PWLD   1088          // proj_w padded cols (17*64)
#define PI_F   3.14159265358979323846f

// ---------------- scratch ----------------
__device__ float g_magp[ROWS*KPAD];     // padded mag (zeros in 513..527)
__device__ float g_cosp[ROWS*FBINS];
__device__ float g_sinp[ROWS*FBINS];
__device__ float g_xg  [ROWS*N3H];
__device__ float g_hs  [ROWS*HDIM];
__device__ float g_gb  [ROWS*2*FBINS];
__device__ float g_y   [ROWS*NFFT];
__device__ float g_embrow[BATCH*N3H];
__device__ float g_wsum[CHUNK];
__device__ float g_wxp [KPAD*N3H];      // padded gru_wx[:FBINS]
__device__ float g_pwp [HDIM*PWLD];     // padded proj_w
__device__ float g_twr[512], g_twi[512];
__device__ float g_win[NFFT];

__device__ __forceinline__ float sigf(float x) { return 1.f/(1.f + expf(-x)); }

// ---------------- tables: twiddles, window, wsum ----------------
__global__ void k_tables() {
    int i = blockIdx.x*blockDim.x + threadIdx.x;
    if (i < 512) {
        float s, c; sincosf(-(2.f*PI_F/NFFT)*i, &s, &c);
        g_twr[i] = c; g_twi[i] = s;
    }
    if (i < NFFT)
        g_win[i] = 0.5f - 0.5f*cosf((2.f*PI_F/NFFT)*i);
    if (i < CHUNK) {
        float ws = 0.f;
        for (int fi = 0; fi < NF; fi++) {
            int d = i - fi*HOP;
            if (d >= 0 && d < NFFT) {
                float w = 0.5f - 0.5f*cosf((2.f*PI_F/NFFT)*d);
                ws += w*w;
            }
        }
        g_wsum[i] = ws;
    }
}

// ---------------- pad weights ----------------
__global__ void k_prep_wx(const float* __restrict__ wx) {
    int i = blockIdx.x*blockDim.x + threadIdx.x;
    if (i >= KPAD*N3H) return;
    int k = i / N3H, n = i % N3H;
    g_wxp[i] = (k < FBINS) ? wx[k*N3H + n] : 0.f;
}
__global__ void k_prep_pw(const float* __restrict__ pw) {
    int i = blockIdx.x*blockDim.x + threadIdx.x;
    if (i >= HDIM*PWLD) return;
    int k = i / PWLD, n = i % PWLD;
    g_pwp[i] = (n < 2*FBINS) ? pw[k*2*FBINS + n] : 0.f;
}

// ---------------- per-batch embedding contribution ----------------
__global__ void k_embrow(const float* __restrict__ emb_table,
                         const float* __restrict__ wx,
                         const int*   __restrict__ effect_id) {
    __shared__ float se[EDIM];
    int b = blockIdx.x;
    int j = threadIdx.x;
    if (j < EDIM) se[j] = emb_table[effect_id[b]*EDIM + j];
    __syncthreads();
    float acc = 0.f;
    #pragma unroll 8
    for (int k = 0; k < EDIM; k++)
        acc += se[k] * wx[(FBINS + k)*N3H + j];
    g_embrow[b*N3H + j] = acc;
}

// ---------------- forward STFT ----------------
__global__ void k_fwdfft(const float* __restrict__ audio) {
    __shared__ float sr[NFFT], si[NFFT];
    __shared__ float twr[512], twi[512];
    const int fr  = blockIdx.x;
    const int tid = threadIdx.x;
    const int b   = fr / CPB;
    const int rem = fr % CPB;
    const int base = (rem/NF)*STRIDE + (rem%NF)*HOP;

    for (int k = tid; k < 512; k += 256) { twr[k] = g_twr[k]; twi[k] = g_twi[k]; }
    for (int n = tid; n < NFFT; n += 256) {
        int s = base + n;
        float v = (s < TSZ) ? audio[b*TSZ + s] : 0.f;
        int j = __brev((unsigned)n) >> 22;
        sr[j] = v*g_win[n]; si[j] = 0.f;
    }
    __syncthreads();
    for (int s = 1; s <= 10; s++) {
        int half = 1 << (s-1);
        for (int t = tid; t < 512; t += 256) {
            int pos = t & (half-1);
            int grp = t >> (s-1);
            int i1 = (grp << s) + pos;
            int i2 = i1 + half;
            int ti_ = pos << (10 - s);
            float wr = twr[ti_], wi = twi[ti_];
            float xr = sr[i2], xi = si[i2];
            float tr = wr*xr - wi*xi;
            float tq = wr*xi + wi*xr;
            sr[i2] = sr[i1] - tr; si[i2] = si[i1] - tq;
            sr[i1] += tr;         si[i1] += tq;
        }
        __syncthreads();
    }
    for (int k = tid; k < KPAD; k += 256) {
        if (k < FBINS) {
            float re = sr[k], im = si[k];
            float mag = sqrtf(re*re + im*im);
            float c, s2;
            if (mag > 1e-30f) { float inv = 1.f/mag; c = re*inv; s2 = im*inv; }
            else              { c = 1.f; s2 = 0.f; }
            g_magp[fr*KPAD + k] = mag;
            g_cosp[fr*FBINS + k] = c;
            g_sinp[fr*FBINS + k] = s2;
        } else {
            g_magp[fr*KPAD + k] = 0.f;
        }
    }
}

// ---------------- xg = mag @ Wx + embrow : M=ROWS N=768 K=528 ----------------
// 128x64 block tile, 8x4 per thread, BK=16, register-staged pipeline
__global__ __launch_bounds__(256) void k_xg() {
    __shared__ float As[16][132];
    __shared__ float Bs[16][68];
    const int tid = threadIdx.x;
    const int tx = tid & 15, ty = tid >> 4;
    const int m0 = blockIdx.y * 128, n0 = blockIdx.x * 64;
    const int am = (tid + 0*256) >> 2, akq0 = (tid) & 3;          // A float4 slots
    const int am1 = (tid + 256) >> 2,  akq1 = (tid + 256) & 3;
    const int bkk = tid >> 4, bnq = tid & 15;                     // B float4 slot

    float4 av0, av1, bv;
    // prologue load k0=0
    {
        int r0 = m0 + am, r1 = m0 + am1;
        av0 = (r0 < ROWS) ? *(const float4*)&g_magp[r0*KPAD + 4*akq0] : make_float4(0,0,0,0);
        av1 = (r1 < ROWS) ? *(const float4*)&g_magp[r1*KPAD + 4*akq1] : make_float4(0,0,0,0);
        bv  = *(const float4*)&g_wxp[bkk*N3H + n0 + 4*bnq];
        As[4*akq0+0][am] = av0.x; As[4*akq0+1][am] = av0.y; As[4*akq0+2][am] = av0.z; As[4*akq0+3][am] = av0.w;
        As[4*akq1+0][am1] = av1.x; As[4*akq1+1][am1] = av1.y; As[4*akq1+2][am1] = av1.z; As[4*akq1+3][am1] = av1.w;
        *(float4*)&Bs[bkk][4*bnq] = bv;
    }
    __syncthreads();

    float acc[8][4] = {};
    #pragma unroll 1
    for (int it = 0; it < 33; it++) {
        if (it < 32) {
            int k0 = (it+1)*16;
            int r0 = m0 + am, r1 = m0 + am1;
            av0 = (r0 < ROWS) ? *(const float4*)&g_magp[r0*KPAD + k0 + 4*akq0] : make_float4(0,0,0,0);
            av1 = (r1 < ROWS) ? *(const float4*)&g_magp[r1*KPAD + k0 + 4*akq1] : make_float4(0,0,0,0);
            bv  = *(const float4*)&g_wxp[(k0+bkk)*N3H + n0 + 4*bnq];
        }
        #pragma unroll
        for (int kk = 0; kk < 16; kk++) {
            float4 a0 = *(float4*)&As[kk][ty*8];
            float4 a1 = *(float4*)&As[kk][ty*8 + 4];
            float4 b  = *(float4*)&Bs[kk][tx*4];
            float ar[8] = {a0.x,a0.y,a0.z,a0.w,a1.x,a1.y,a1.z,a1.w};
            float br[4] = {b.x,b.y,b.z,b.w};
            #pragma unroll
            for (int i = 0; i < 8; i++)
                #pragma unroll
                for (int j = 0; j < 4; j++)
                    acc[i][j] += ar[i]*br[j];
        }
        __syncthreads();
        if (it < 32) {
            As[4*akq0+0][am] = av0.x; As[4*akq0+1][am] = av0.y; As[4*akq0+2][am] = av0.z; As[4*akq0+3][am] = av0.w;
            As[4*akq1+0][am1] = av1.x; As[4*akq1+1][am1] = av1.y; As[4*akq1+2][am1] = av1.z; As[4*akq1+3][am1] = av1.w;
            *(float4*)&Bs[bkk][4*bnq] = bv;
            __syncthreads();
        }
    }
    #pragma unroll
    for (int i = 0; i < 8; i++) {
        int row = m0 + ty*8 + i;
        if (row >= ROWS) continue;
        int b = row / CPB;
        const float* er = &g_embrow[b*N3H];
        #pragma unroll
        for (int j = 0; j < 4; j++) {
            int col = n0 + tx*4 + j;
            g_xg[row*N3H + col] = acc[i][j] + er[col];
        }
    }
}

// ---------------- one GRU step ----------------
__global__ void k_gru(const float* __restrict__ wh,
                      const float* __restrict__ gbias, int t) {
    __shared__ float As[16][33];
    __shared__ float Bs[3][16][65];
    const int sq0 = blockIdx.y * 32;
    const int c0  = blockIdx.x * 64;
    const int tid = threadIdx.x;
    const int ty = tid >> 4, tx = tid & 15;
    float acc[3][2][4] = {};
    if (t > 0) {
        for (int k0 = 0; k0 < HDIM; k0 += 16) {
            #pragma unroll
            for (int i = 0; i < 2; i++) {
                int lin = tid + i*256;
                int mm = lin >> 4, kk = lin & 15;
                int sq = sq0 + mm;
                As[kk][mm] = (sq < SEQ) ? g_hs[(sq*NF + t - 1)*HDIM + k0 + kk] : 0.f;
            }
            #pragma unroll
            for (int i = 0; i < 12; i++) {
                int lin = tid + i*256;
                int gg = lin >> 10;
                int r2 = lin & 1023;
                int kk = r2 >> 6, nn = r2 & 63;
                Bs[gg][kk][nn] = wh[(k0+kk)*N3H + gg*HDIM + c0 + nn];
            }
            __syncthreads();
            #pragma unroll
            for (int kk = 0; kk < 16; kk++) {
                float a0 = As[kk][ty*2], a1 = As[kk][ty*2 + 1];
                #pragma unroll
                for (int gg = 0; gg < 3; gg++) {
                    #pragma unroll
                    for (int j = 0; j < 4; j++) {
                        float bvv = Bs[gg][kk][tx*4 + j];
                        acc[gg][0][j] += a0*bvv;
                        acc[gg][1][j] += a1*bvv;
                    }
                }
            }
            __syncthreads();
        }
    }
    #pragma unroll
    for (int i = 0; i < 2; i++) {
        int sq = sq0 + ty*2 + i;
        if (sq >= SEQ) continue;
        const float* xg = &g_xg[(sq*NF + t)*N3H];
        int hbase = (sq*NF + t)*HDIM;
        int pbase = (sq*NF + t - 1)*HDIM;
        #pragma unroll
        for (int j = 0; j < 4; j++) {
            int c = c0 + tx*4 + j;
            float z = sigf(xg[c]           + acc[0][i][j] + gbias[c]);
            float r = sigf(xg[HDIM + c]    + acc[1][i][j] + gbias[HDIM + c]);
            float n = tanhf(xg[2*HDIM + c] + r*(acc[2][i][j] + gbias[2*HDIM + c]));
            float hp = (t > 0) ? g_hs[pbase + c] : 0.f;
            g_hs[hbase + c] = (1.f - z)*n + z*hp;
        }
    }
}

// ---------------- proj: gb = hs @ proj_w + b : M=ROWS N=1026(pad 1088) K=256 ----------------
__global__ __launch_bounds__(256) void k_proj(const float* __restrict__ pb) {
    __shared__ float As[16][132];
    __shared__ float Bs[16][68];
    const int tid = threadIdx.x;
    const int tx = tid & 15, ty = tid >> 4;
    const int m0 = blockIdx.y * 128, n0 = blockIdx.x * 64;
    const int am = (tid) >> 2,      akq0 = (tid) & 3;
    const int am1 = (tid + 256) >> 2, akq1 = (tid + 256) & 3;
    const int bkk = tid >> 4, bnq = tid & 15;

    float4 av0, av1, bv;
    {
        int r0 = m0 + am, r1 = m0 + am1;
        av0 = (r0 < ROWS) ? *(const float4*)&g_hs[r0*HDIM + 4*akq0] : make_float4(0,0,0,0);
        av1 = (r1 < ROWS) ? *(const float4*)&g_hs[r1*HDIM + 4*akq1] : make_float4(0,0,0,0);
        bv  = *(const float4*)&g_pwp[bkk*PWLD + n0 + 4*bnq];
        As[4*akq0+0][am] = av0.x; As[4*akq0+1][am] = av0.y; As[4*akq0+2][am] = av0.z; As[4*akq0+3][am] = av0.w;
        As[4*akq1+0][am1] = av1.x; As[4*akq1+1][am1] = av1.y; As[4*akq1+2][am1] = av1.z; As[4*akq1+3][am1] = av1.w;
        *(float4*)&Bs[bkk][4*bnq] = bv;
    }
    __syncthreads();

    float acc[8][4] = {};
    #pragma unroll 1
    for (int it = 0; it < 16; it++) {
        if (it < 15) {
            int k0 = (it+1)*16;
            int r0 = m0 + am, r1 = m0 + am1;
            av0 = (r0 < ROWS) ? *(const float4*)&g_hs[r0*HDIM + k0 + 4*akq0] : make_float4(0,0,0,0);
            av1 = (r1 < ROWS) ? *(const float4*)&g_hs[r1*HDIM + k0 + 4*akq1] : make_float4(0,0,0,0);
            bv  = *(const float4*)&g_pwp[(k0+bkk)*PWLD + n0 + 4*bnq];
        }
        #pragma unroll
        for (int kk = 0; kk < 16; kk++) {
            float4 a0 = *(float4*)&As[kk][ty*8];
            float4 a1 = *(float4*)&As[kk][ty*8 + 4];
            float4 b  = *(float4*)&Bs[kk][tx*4];
            float ar[8] = {a0.x,a0.y,a0.z,a0.w,a1.x,a1.y,a1.z,a1.w};
            float br[4] = {b.x,b.y,b.z,b.w};
            #pragma unroll
            for (int i = 0; i < 8; i++)
                #pragma unroll
                for (int j = 0; j < 4; j++)
                    acc[i][j] += ar[i]*br[j];
        }
        __syncthreads();
        if (it < 15) {
            As[4*akq0+0][am] = av0.x; As[4*akq0+1][am] = av0.y; As[4*akq0+2][am] = av0.z; As[4*akq0+3][am] = av0.w;
            As[4*akq1+0][am1] = av1.x; As[4*akq1+1][am1] = av1.y; As[4*akq1+2][am1] = av1.z; As[4*akq1+3][am1] = av1.w;
            *(float4*)&Bs[bkk][4*bnq] = bv;
            __syncthreads();
        }
    }
    #pragma unroll
    for (int i = 0; i < 8; i++) {
        int row = m0 + ty*8 + i;
        if (row >= ROWS) continue;
        #pragma unroll
        for (int j = 0; j < 4; j++) {
            int col = n0 + tx*4 + j;
            if (col < 2*FBINS)
                g_gb[row*2*FBINS + col] = acc[i][j] + pb[col];
        }
    }
}

// ---------------- modulate + inverse FFT + window ----------------
__global__ void k_modinv() {
    __shared__ float sre[FBINS], sim[FBINS];
    __shared__ float sr[NFFT], si[NFFT];
    __shared__ float twr[512], twi[512];
    const int fr  = blockIdx.x;
    const int tid = threadIdx.x;

    for (int k = tid; k < 512; k += 256) { twr[k] = g_twr[k]; twi[k] = g_twi[k]; }
    for (int k = tid; k < FBINS; k += 256) {
        float mag   = g_magp[fr*KPAD + k];
        float gamma = g_gb[fr*2*FBINS + k];
        float beta  = g_gb[fr*2*FBINS + FBINS + k];
        float mm = gamma*mag + beta;
        sre[k] = mm * g_cosp[fr*FBINS + k];
        sim[k] = mm * g_sinp[fr*FBINS + k];
    }
    __syncthreads();
    for (int n = tid; n < NFFT; n += 256) {
        float re, im;
        if (n <= 512) { re = sre[n];        im =  sim[n]; }
        else          { re = sre[NFFT - n]; im = -sim[NFFT - n]; }
        int j = __brev((unsigned)n) >> 22;
        sr[j] = re; si[j] = im;
    }
    __syncthreads();
    for (int s = 1; s <= 10; s++) {
        int half = 1 << (s-1);
        for (int t = tid; t < 512; t += 256) {
            int pos = t & (half-1);
            int grp = t >> (s-1);
            int i1 = (grp << s) + pos;
            int i2 = i1 + half;
            int ti_ = pos << (10 - s);
            float wr = twr[ti_], wi = -twi[ti_];
            float xr = sr[i2], xi = si[i2];
            float tr = wr*xr - wi*xi;
            float tq = wr*xi + wi*xr;
            sr[i2] = sr[i1] - tr; si[i2] = si[i1] - tq;
            sr[i1] += tr;         si[i1] += tq;
        }
        __syncthreads();
    }
    const float invn = 1.f/(float)NFFT;
    for (int n = tid; n < NFFT; n += 256)
        g_y[fr*NFFT + n] = sr[n]*invn*g_win[n];
}

// ---------------- overlap-add ----------------
__global__ void k_overlap(float* __restrict__ out) {
    const int t = blockIdx.x*blockDim.x + threadIdx.x;
    const int b = blockIdx.y;
    if (t >= TSZ) return;
    int ci_hi = t / STRIDE; if (ci_hi > NCH-1) ci_hi = NCH-1;
    int v = t - (CHUNK - 1);
    int ci_lo = (v <= 0) ? 0 : (v + STRIDE - 1)/STRIDE;
    float acc = 0.f;
    for (int ci = ci_lo; ci <= ci_hi; ci++) {
        int n = t - ci*STRIDE;
        int fi_hi = n >> 8; if (fi_hi > NF-1) fi_hi = NF-1;
        int w = n - (NFFT - 1);
        int fi_lo = (w <= 0) ? 0 : (w + HOP - 1) >> 8;
        float s = 0.f;
        for (int fi = fi_lo; fi <= fi_hi; fi++)
            s += g_y[(((b*NCH + ci)*NF) + fi)*NFFT + n - fi*HOP];
        acc += s / fmaxf(g_wsum[n], 1e-8f);
    }
    out[b*TSZ + t] = acc;
}

// ---------------- launch ----------------
extern "C" void kernel_launch(void* const* d_in, const int* in_sizes, int n_in,
                              void* d_out, int out_size) {
    const float* audio     = (const float*)d_in[0];
    const float* emb_table = (const float*)d_in[1];
    const float* gru_wx    = (const float*)d_in[2];
    const float* gru_wh    = (const float*)d_in[3];
    const float* gru_b     = (const float*)d_in[4];
    const float* proj_w    = (const float*)d_in[5];
    const float* proj_b    = (const float*)d_in[6];
    const int*   effect_id = (const int*)  d_in[7];
    float* out = (float*)d_out;

    k_tables<<<(CHUNK + 255)/256, 256>>>();
    k_prep_wx<<<(KPAD*N3H + 255)/256, 256>>>(gru_wx);
    k_prep_pw<<<(HDIM*PWLD + 255)/256, 256>>>(proj_w);
    k_embrow<<<BATCH, N3H>>>(emb_table, gru_wx, effect_id);
    k_fwdfft<<<ROWS, 256>>>(audio);
    k_xg<<<dim3(N3H/64, (ROWS + 127)/128), 256>>>();
    for (int t = 0; t < NF; t++)
        k_gru<<<dim3(HDIM/64, (SEQ + 31)/32), 256>>>(gru_wh, gru_b, t);
    k_proj<<<dim3(PWLD/64, (ROWS + 127)/128), 256>>>(proj_b);
    k_modinv<<<ROWS, 256>>>();
    k_overlap<<<dim3((TSZ + 255)/256, BATCH), 256>>>(out);
}